// round 14
// baseline (speedup 1.0000x reference)
#include <cuda_runtime.h>
#include <cuda_fp16.h>
#include <cstdint>

#define N_PTS   32768
#define DIM     256
#define KCODES  1024
#define DECAYF  0.99f
#define OMDECAY 0.01f
#define EPSF    1e-5f
#define MARGIN  2.0f
#define CMAX    16

// Output layout (concatenated, float32)
#define OFF_ZQ    0
#define OFF_LOSS  (N_PTS * DIM)
#define OFF_IDX   (OFF_LOSS + 1)
#define OFF_EMB   (OFF_IDX + N_PTS)
#define OFF_CS    (OFF_EMB + KCODES * DIM)
#define OFF_EMAW  (OFF_CS + KCODES)

__device__ float  g_enorm[KCODES];
__device__ float  g_loss;
__device__ float  g_n;
__device__ __half g_zh[N_PTS * DIM];
__device__ __half g_eh[KCODES * DIM];
__device__ int    g_sel[N_PTS];
__device__ int    g_cnt[KCODES];
__device__ int    g_off[KCODES];
__device__ int    g_fill[KCODES];
__device__ int    g_bkt[N_PTS];

// ---------------------------------------------------------------------------
// helpers
// ---------------------------------------------------------------------------
__device__ __forceinline__ uint32_t smem_u32(const void* p) {
    uint32_t a;
    asm("{ .reg .u64 t; cvta.to.shared.u64 t, %1; cvt.u32.u64 %0, t; }"
        : "=r"(a) : "l"(p));
    return a;
}
__device__ __forceinline__ void cp16(uint32_t dst, const void* src) {
    asm volatile("cp.async.cg.shared.global [%0], [%1], 16;"
                 :: "r"(dst), "l"(__cvta_generic_to_global(src)) : "memory");
}
#define CP_COMMIT() asm volatile("cp.async.commit_group;" ::: "memory")

#define LDSM_X4(r0, r1, r2, r3, a) \
    asm volatile("ldmatrix.sync.aligned.m8n8.x4.shared.b16 {%0,%1,%2,%3}, [%4];" \
                 : "=r"(r0), "=r"(r1), "=r"(r2), "=r"(r3) : "r"(a))
#define LDSM_X2(r0, r1, a) \
    asm volatile("ldmatrix.sync.aligned.m8n8.x2.shared.b16 {%0,%1}, [%2];" \
                 : "=r"(r0), "=r"(r1) : "r"(a))

__device__ __forceinline__ void mma16816(float* c, const uint32_t* a, const uint32_t* b) {
    asm volatile("mma.sync.aligned.m16n8k16.row.col.f32.f16.f16.f32 "
                 "{%0,%1,%2,%3}, {%4,%5,%6,%7}, {%8,%9}, {%0,%1,%2,%3};"
                 : "+f"(c[0]), "+f"(c[1]), "+f"(c[2]), "+f"(c[3])
                 : "r"(a[0]), "r"(a[1]), "r"(a[2]), "r"(a[3]), "r"(b[0]), "r"(b[1]));
}

// ---------------------------------------------------------------------------
// k_prep: fp32 -> fp16 (vectorized 4/thread); zero counters
// ---------------------------------------------------------------------------
__global__ void k_prep(const float* __restrict__ z, const float* __restrict__ e) {
    int idx = blockIdx.x * blockDim.x + threadIdx.x;     // covers N*D/4
    int i4 = idx * 4;
    float4 v = *(const float4*)(z + i4);
    __half2* zp = (__half2*)(g_zh + i4);
    zp[0] = __floats2half2_rn(v.x, v.y);
    zp[1] = __floats2half2_rn(v.z, v.w);
    if (i4 < KCODES * DIM) {
        float4 w = *(const float4*)(e + i4);
        __half2* ep = (__half2*)(g_eh + i4);
        ep[0] = __floats2half2_rn(w.x, w.y);
        ep[1] = __floats2half2_rn(w.z, w.w);
    }
    if (idx < KCODES) { g_cnt[idx] = 0; g_fill[idx] = 0; }
    if (idx == 0) g_loss = 0.0f;
}

__global__ void k_norm(const float* __restrict__ emb) {
    int warp = (blockIdx.x * blockDim.x + threadIdx.x) >> 5;
    int lane = threadIdx.x & 31;
    if (warp >= KCODES) return;
    const float4* row = (const float4*)(emb + (size_t)warp * DIM);
    float4 a = row[lane * 2 + 0];
    float4 b = row[lane * 2 + 1];
    float s = a.x*a.x + a.y*a.y + a.z*a.z + a.w*a.w
            + b.x*b.x + b.y*b.y + b.z*b.z + b.w*b.w;
#pragma unroll
    for (int off = 16; off; off >>= 1) s += __shfl_down_sync(0xFFFFFFFFu, s, off);
    if (lane == 0) g_enorm[warp] = s;
}

// ---------------------------------------------------------------------------
// Fused kernel: block = 64 points x ALL 1024 codes.
// z tile resident; e tiles double-buffered; approx distances staged to a
// 64x1024 fp16 SMEM slab. Then FULL-ROW min -> margin candidates (bounded,
// fixes R13 running-min overflow), exact fp32 rescore, gather, loss, counts.
// ---------------------------------------------------------------------------
#define A_ROWB   528                           // 256 halves + 16B pad
#define A_OFF    0
#define A_BYTES  (64 * A_ROWB)                 // 33792
#define B_ROWB   144                           // 64 halves + 16B pad
#define B_OFF(s) (A_BYTES + (s) * (128 * B_ROWB))
#define EN_OFF   (A_BYTES + 2 * 128 * B_ROWB)  // 70656
#define D_OFF    (EN_OFF + 512)                // 71168
#define D_ROWB   2064                          // 1024 halves + 16B pad
#define CT_OFF   (D_OFF + 64 * D_ROWB)         // 203264
#define CD_OFF   (CT_OFF + 256)                // 203520
#define SMEM_SZ  (CD_OFF + 64 * CMAX * 4)      // 207616

__global__ __launch_bounds__(256, 1) void k_fused(const float* __restrict__ z,
                                                  const float* __restrict__ emb,
                                                  float* __restrict__ out) {
    extern __shared__ char smem[];
    uint32_t sb = smem_u32(smem);
    int tid  = threadIdx.x;
    int wid  = tid >> 5;
    int lane = tid & 31;
    int m0   = blockIdx.x * 64;
    int warp_m = wid & 1;        // 2 x 32 rows
    int warp_n = wid >> 1;       // 4 x 32 cols (of 128-wide tile)

    float* en   = (float*)(smem + EN_OFF);
    int*   ccnt = (int*)(smem + CT_OFF);
    int*   cand = (int*)(smem + CD_OFF);

    // resident A (z tile): 64 rows x 512B = 2048 x 16B chunks
#pragma unroll
    for (int i = 0; i < 8; i++) {
        int ch = tid + i * 256;
        int r = ch >> 5, sg = ch & 31;
        cp16(sb + A_OFF + r * A_ROWB + sg * 16,
             g_zh + (size_t)(m0 + r) * DIM + sg * 8);
    }
    CP_COMMIT();
    if (tid < 64) ccnt[tid] = 0;

    // ldmatrix lane invariants
    int rA  = warp_m * 32 + (lane & 7) + (((lane >> 3) & 1) << 3);
    int cA8 = ((lane >> 4) & 1) << 3;
    int rB  = warp_n * 32 + (lane & 7);
    int cB8 = ((lane >> 3) & 1) << 3;

    for (int nt = 0; nt < 8; nt++) {
        int n0 = nt * 128;

        // prefetch B chunks 0,1 (each: 128 rows x 128B = 1024 x 16B)
#pragma unroll
        for (int s = 0; s < 2; s++) {
#pragma unroll
            for (int i = 0; i < 4; i++) {
                int ch = tid + i * 256;
                int r = ch >> 3, sg = ch & 7;
                cp16(sb + B_OFF(s) + r * B_ROWB + sg * 16,
                     g_eh + (size_t)(n0 + r) * DIM + s * 64 + sg * 8);
            }
            CP_COMMIT();
        }
        if (tid < 128) en[tid] = g_enorm[n0 + tid];

        float acc[2][4][4] = {};

        for (int kc = 0; kc < 4; kc++) {
            int s = kc & 1;
            if (kc < 3) asm volatile("cp.async.wait_group 1;" ::: "memory");
            else        asm volatile("cp.async.wait_group 0;" ::: "memory");
            __syncthreads();

#pragma unroll
            for (int ks = 0; ks < 4; ks++) {
                int k0g = kc * 64 + ks * 16;
                uint32_t a[2][4], b[4][2];
#pragma unroll
                for (int mi = 0; mi < 2; mi++) {
                    uint32_t ad = sb + A_OFF + (rA + mi * 16) * A_ROWB + (k0g + cA8) * 2;
                    LDSM_X4(a[mi][0], a[mi][1], a[mi][2], a[mi][3], ad);
                }
#pragma unroll
                for (int nj = 0; nj < 4; nj++) {
                    uint32_t bd = sb + B_OFF(s) + (rB + nj * 8) * B_ROWB + (ks * 16 + cB8) * 2;
                    LDSM_X2(b[nj][0], b[nj][1], bd);
                }
#pragma unroll
                for (int mi = 0; mi < 2; mi++)
#pragma unroll
                    for (int nj = 0; nj < 4; nj++)
                        mma16816(acc[mi][nj], a[mi], b[nj]);
            }
            __syncthreads();
            if (kc + 2 < 4) {
#pragma unroll
                for (int i = 0; i < 4; i++) {
                    int ch = tid + i * 256;
                    int r = ch >> 3, sg = ch & 7;
                    cp16(sb + B_OFF(s) + r * B_ROWB + sg * 16,
                         g_eh + (size_t)(n0 + r) * DIM + (kc + 2) * 64 + sg * 8);
                }
                CP_COMMIT();
            }
        }

        // stage distances into smem slab (conflict-free: bank = 4*(lane>>2)+(lane&3))
#pragma unroll
        for (int mi = 0; mi < 2; mi++) {
#pragma unroll
            for (int nj = 0; nj < 4; nj++) {
                int cw = warp_n * 32 + nj * 8 + (lane & 3) * 2;
                int r0 = warp_m * 32 + mi * 16 + (lane >> 2);
                float e0 = en[cw], e1 = en[cw + 1];
                __half2 v0 = __floats2half2_rn(e0 - 2.0f * acc[mi][nj][0],
                                               e1 - 2.0f * acc[mi][nj][1]);
                __half2 v1 = __floats2half2_rn(e0 - 2.0f * acc[mi][nj][2],
                                               e1 - 2.0f * acc[mi][nj][3]);
                *(__half2*)(smem + D_OFF + r0 * D_ROWB + (n0 + cw) * 2) = v0;
                *(__half2*)(smem + D_OFF + (r0 + 8) * D_ROWB + (n0 + cw) * 2) = v1;
            }
        }
        __syncthreads();
    }

    // ---- selection: warp per point (8 points/warp), full-row min first ----
    float lsum = 0.0f;
    for (int i = 0; i < 8; i++) {
        int p = wid * 8 + i;
        int n = m0 + p;
        const char* row = smem + D_OFF + p * D_ROWB;

        uint4 u[4];
        float vmin = 3.4e38f;
#pragma unroll
        for (int sg = 0; sg < 4; sg++) {
            u[sg] = *(const uint4*)(row + lane * 16 + sg * 512);
            const uint32_t* ww = (const uint32_t*)&u[sg];
#pragma unroll
            for (int j = 0; j < 4; j++) {
                float2 f = __half22float2(*(const __half2*)&ww[j]);
                vmin = fminf(vmin, fminf(f.x, f.y));
            }
        }
#pragma unroll
        for (int off = 16; off; off >>= 1)
            vmin = fminf(vmin, __shfl_xor_sync(0xFFFFFFFFu, vmin, off));
        float thr = vmin + MARGIN;

#pragma unroll
        for (int sg = 0; sg < 4; sg++) {
            const uint32_t* ww = (const uint32_t*)&u[sg];
#pragma unroll
            for (int j = 0; j < 4; j++) {
                float2 f = __half22float2(*(const __half2*)&ww[j]);
                int c0 = sg * 256 + lane * 8 + j * 2;
                if (f.x <= thr) { int q = atomicAdd(&ccnt[p], 1); if (q < CMAX) cand[p * CMAX + q] = c0; }
                if (f.y <= thr) { int q = atomicAdd(&ccnt[p], 1); if (q < CMAX) cand[p * CMAX + q] = c0 + 1; }
            }
        }
        __syncwarp();
        int ccap = min(ccnt[p], CMAX);

        // exact fp32 rescore
        const float4* zr = (const float4*)(z + (size_t)n * DIM);
        float4 za = zr[lane * 2], zb = zr[lane * 2 + 1];
        float bd = 3.4e38f;
        int bc = 0x7FFFFFFF;
        for (int t = 0; t < ccap; t++) {
            int c = cand[p * CMAX + t];
            const float4* er = (const float4*)(emb + (size_t)c * DIM);
            float4 ea = er[lane * 2], eb = er[lane * 2 + 1];
            float s = za.x*ea.x + za.y*ea.y + za.z*ea.z + za.w*ea.w
                    + zb.x*eb.x + zb.y*eb.y + zb.z*eb.z + zb.w*eb.w;
#pragma unroll
            for (int off = 16; off; off >>= 1)
                s += __shfl_xor_sync(0xFFFFFFFFu, s, off);
            float d = g_enorm[c] - 2.0f * s;
            if (d < bd || (d == bd && c < bc)) { bd = d; bc = c; }
        }

        // gather chosen row + loss
        const float4* er = (const float4*)(emb + (size_t)bc * DIM);
        float4 ea = er[lane * 2], eb = er[lane * 2 + 1];
        float4* zq = (float4*)(out + OFF_ZQ + (size_t)n * DIM);
        zq[lane * 2]     = ea;
        zq[lane * 2 + 1] = eb;
        float dx = za.x-ea.x, dy = za.y-ea.y, dz = za.z-ea.z, dw = za.w-ea.w;
        lsum += dx*dx + dy*dy + dz*dz + dw*dw;
        dx = zb.x-eb.x; dy = zb.y-eb.y; dz = zb.z-eb.z; dw = zb.w-eb.w;
        lsum += dx*dx + dy*dy + dz*dz + dw*dw;

        if (lane == 0) {
            out[OFF_IDX + n] = (float)bc;
            g_sel[n] = bc;
            atomicAdd(&g_cnt[bc], 1);
        }
    }
#pragma unroll
    for (int off = 16; off; off >>= 1)
        lsum += __shfl_down_sync(0xFFFFFFFFu, lsum, off);
    if (lane == 0) atomicAdd(&g_loss, lsum);
}

// ---------------------------------------------------------------------------
// k_off: exclusive prefix of counts; write new_cluster_size
// ---------------------------------------------------------------------------
__global__ void k_off(const float* __restrict__ ema_cs, float* __restrict__ out) {
    __shared__ int sh[KCODES];
    int t = threadIdx.x;
    int v = g_cnt[t];
    out[OFF_CS + t] = DECAYF * ema_cs[t] + OMDECAY * (float)v;
    sh[t] = v;
    __syncthreads();
    for (int off = 1; off < KCODES; off <<= 1) {
        int x = (t >= off) ? sh[t - off] : 0;
        __syncthreads();
        sh[t] += x;
        __syncthreads();
    }
    g_off[t] = sh[t] - v;
}

__global__ void k_fill() {
    int n = blockIdx.x * blockDim.x + threadIdx.x;
    int c = g_sel[n];
    int pos = g_off[c] + atomicAdd(&g_fill[c], 1);
    g_bkt[pos] = n;
}

__global__ __launch_bounds__(256) void k_dw(const float* __restrict__ z,
                                            const float* __restrict__ ema_w,
                                            float* __restrict__ out) {
    int c = blockIdx.x;
    int d = threadIdx.x;
    int beg = g_off[c], cnt = g_cnt[c];
    float acc = 0.0f;
    for (int m = 0; m < cnt; m++) {
        int p = g_bkt[beg + m];
        acc += z[(size_t)p * DIM + d];
    }
    out[OFF_EMAW + (size_t)c * DIM + d] =
        DECAYF * ema_w[(size_t)c * DIM + d] + OMDECAY * acc;
}

__global__ void k_nsum(const float* __restrict__ out) {
    __shared__ float sh[32];
    int t = threadIdx.x;
    float v = out[OFF_CS + t];
#pragma unroll
    for (int off = 16; off; off >>= 1) v += __shfl_down_sync(0xFFFFFFFFu, v, off);
    if ((t & 31) == 0) sh[t >> 5] = v;
    __syncthreads();
    if (t < 32) {
        float s = sh[t];
#pragma unroll
        for (int off = 16; off; off >>= 1) s += __shfl_down_sync(0xFFFFFFFFu, s, off);
        if (t == 0) g_n = s;
    }
}

__global__ void k_final(float* __restrict__ out) {
    int i = blockIdx.x * blockDim.x + threadIdx.x;
    float n = g_n;
    int k = i >> 8;
    float cs = (out[OFF_CS + k] + EPSF) / (n + (float)KCODES * EPSF) * n;
    out[OFF_EMB + i] = out[OFF_EMAW + i] / cs;
    if (i == 0)
        out[OFF_LOSS] = 1.25f * g_loss / (float)(N_PTS * DIM);
}

// ---------------------------------------------------------------------------
extern "C" void kernel_launch(void* const* d_in, const int* in_sizes, int n_in,
                              void* d_out, int out_size) {
    const float* z      = (const float*)d_in[0];
    const float* emb    = (const float*)d_in[1];
    const float* ema_cs = (const float*)d_in[2];
    const float* ema_w  = (const float*)d_in[3];
    float* out = (float*)d_out;

    cudaFuncSetAttribute(k_fused,
                         cudaFuncAttributeMaxDynamicSharedMemorySize, SMEM_SZ);

    k_prep<<<(N_PTS * DIM / 4) / 256, 256>>>(z, emb);
    k_norm<<<(KCODES * 32) / 256, 256>>>(emb);
    k_fused<<<N_PTS / 64, 256, SMEM_SZ>>>(z, emb, out);
    k_off<<<1, KCODES>>>(ema_cs, out);
    k_fill<<<N_PTS / 256, 256>>>();
    k_dw<<<KCODES, 256>>>(z, ema_w, out);
    k_nsum<<<1, 1024>>>(out);
    k_final<<<(KCODES * DIM) / 256, 256>>>(out);
}